// round 14
// baseline (speedup 1.0000x reference)
#include <cuda_runtime.h>
#include <cuda_fp16.h>
#include <cstdint>

// ResidualKANBlock via SPARSE mma.sp::ordered_metadata m16n8k32 (2:4), f32 accum.
// Per dim: 16 dense slots (permuted so any basis window + silu is 2:4-legal),
// compressed to 8 halves + 16-bit metadata. 8 dims/chunk (dense K=128), 16 chunks.

#define NTOK   65536
#define TM     64
#define NCTA   (NTOK / TM)
#define NCHUNK 16
#define LN_EPS 1e-5f

#define APITCH 144                   // compressed A row: 64 halves + pad (16B align, bank-safe)
#define WPITCH 272                   // W row: 128 halves + pad
#define ABUF   (64 * APITCH)         // 9216
#define WBUF   (128 * WPITCH)        // 34816
#define SM_A0   0
#define SM_A1   ABUF
#define SM_W    (2 * ABUF)
#define SM_META (SM_W + 2 * WBUF)    // 2 x 1024B (u16 meta[8 dims][64 tok])
#define SM_GB   (SM_META + 2048)
#define SM_EPI  (SM_GB + 1024)
#define SM_TOT  (SM_EPI + 1024)      // 92160 B -> occupancy 2

__device__ float          g_xT[128u * 65536u];
__device__ unsigned short g_W[NCHUNK * 128 * (WPITCH / 2)];

// per-ci LUTs (derived from permutation pos[j]={12,5,0,6,1,8,2,9,3,10,4,11,13}, silu=14)
__constant__ unsigned VLUT[16] = {
    0x43FFFFFFu, 0x42FFF3FFu, 0x41FFF2F3u, 0x40FF31F2u,
    0xF4FF2031u, 0xF4F3F120u, 0xF4F2F031u, 0xF431FF20u,
    0xF420FF31u, 0xF431FF20u, 0xF420F31Fu, 0xF431F20Fu,
    0x4320F1FFu, 0x421FF0FFu, 0x410FFFFFu, 0x40FFFFFFu };
__constant__ unsigned short MLUT[16] = {
    0x8EEE, 0x8EDE, 0x8EDC, 0x8E9C, 0xEE94, 0xECE4, 0xECE9, 0xE4E9,
    0xE4EE, 0xE9EE, 0xE9CE, 0xEECE, 0x9ECE, 0x9ECE, 0x9EEE, 0x9EEE };
__constant__ int INVP[16] = {2,4,6,8,10,1,3,-1,5,7,9,11,0,12,-2,-1};

__device__ __forceinline__ unsigned s2u(const void* p) {
    unsigned r;
    asm("{ .reg .u64 t; cvta.to.shared.u64 t, %1; cvt.u32.u64 %0, t; }" : "=r"(r) : "l"(p));
    return r;
}

#define LDSM_X4(r, a) \
    asm volatile("ldmatrix.sync.aligned.m8n8.x4.shared.b16 {%0,%1,%2,%3}, [%4];" \
                 : "=r"((r)[0]), "=r"((r)[1]), "=r"((r)[2]), "=r"((r)[3]) : "r"(a))
#define MMASP(d, a, b, e) \
    asm volatile("mma.sp::ordered_metadata.sync.aligned.m16n8k32.row.col.f32.f16.f16.f32 " \
                 "{%0,%1,%2,%3}, {%4,%5,%6,%7}, {%8,%9,%10,%11}, {%0,%1,%2,%3}, %12, 0x0;" \
                 : "+f"((d)[0]), "+f"((d)[1]), "+f"((d)[2]), "+f"((d)[3]) \
                 : "r"((a)[0]), "r"((a)[1]), "r"((a)[2]), "r"((a)[3]), \
                   "r"((b)[0]), "r"((b)[1]), "r"((b)[2]), "r"((b)[3]), "r"(e))
#define CPASYNC16(dst, src) \
    asm volatile("cp.async.cg.shared.global [%0], [%1], 16;" :: "r"(dst), "l"(src) : "memory")

// ------------------------------------------------------------- prep kernels
__global__ void transpose_x(const float* __restrict__ x) {
    __shared__ float t[32][33];
    int bx = blockIdx.x * 32, by = blockIdx.y * 32;
    int lx = threadIdx.x, ly = threadIdx.y;
    #pragma unroll
    for (int r = 0; r < 32; r += 8)
        t[ly + r][lx] = x[(size_t)(bx + ly + r) * 128 + by + lx];
    __syncthreads();
    #pragma unroll
    for (int r = 0; r < 32; r += 8)
        g_xT[(size_t)(by + ly + r) * 65536 + bx + lx] = t[lx][ly + r];
}

__global__ void prep_w(const float* __restrict__ base_w,
                       const float* __restrict__ spline_w) {
    int idx = blockIdx.x * blockDim.x + threadIdx.x;
    if (idx >= NCHUNK * 128 * (WPITCH / 2)) return;
    int c = idx / (128 * (WPITCH / 2));
    int r = idx % (128 * (WPITCH / 2));
    int n = r / (WPITCH / 2);
    int s = r % (WPITCH / 2);          // 0..135; 128 live
    float v = 0.f;
    if (s < 128) {
        int d = s >> 4, sl = s & 15, i = 8 * c + d;
        int j = INVP[sl];
        if (j >= 0)       v = spline_w[(size_t)n * 1664 + i * 13 + j];
        else if (j == -2) v = base_w[n * 128 + i];
    }
    g_W[(size_t)c * (128 * (WPITCH/2)) + n * (WPITCH/2) + s] =
        __half_as_ushort(__float2half_rn(v));
}

// --------------------------------------------------------------- main kernel
__global__ void __launch_bounds__(256, 2)
kan_mma(const float* __restrict__ x, const float* __restrict__ gamma,
        const float* __restrict__ beta, float* __restrict__ out)
{
    extern __shared__ unsigned char smem[];
    const unsigned sb = s2u(smem);
    const int tid = threadIdx.x;
    const int w = tid >> 5, l = tid & 31;
    const int g = w >> 1, h = w & 1;            // token group / n-half
    const int tok = tid & 63, p = tid >> 6;     // A-build: token, dim-class
    const int tokbase = blockIdx.x * TM;

    if (tid < 128) {
        float2 gb = make_float2(gamma[tid], beta[tid]);
        *(float2*)(smem + SM_GB + tid * 8) = gb;
    }

    const unsigned paL = (unsigned)(l & 15) * APITCH + ((l >> 4) & 1) * 16;
    const unsigned pbL = (unsigned)(l & 7) * WPITCH + ((l >> 3) & 3) * 16;

    float acc[8][4];
    #pragma unroll
    for (int t = 0; t < 8; ++t)
        acc[t][0] = acc[t][1] = acc[t][2] = acc[t][3] = 0.f;

    auto cpW = [&](int c, int buf) {
        const char* src = (const char*)(g_W + (size_t)c * (128 * (WPITCH/2)));
        unsigned dst = sb + SM_W + buf * WBUF;
        #pragma unroll
        for (int k = 0; k < 9; ++k) {
            int i16 = tid + 256 * k;
            if (i16 < WBUF / 16) CPASYNC16(dst + 16 * i16, src + 16 * i16);
        }
        asm volatile("cp.async.commit_group;" ::: "memory");
    };
    cpW(0, 0);

    const float* xpa = g_xT + (size_t)p * 65536 + tokbase + tok;
    const float* xpb = g_xT + (size_t)(p + 4) * 65536 + tokbase + tok;

    auto buildA = [&](unsigned aoff, unsigned moff, float xa, float xb) {
        #pragma unroll
        for (int d2 = 0; d2 < 2; ++d2) {
            float xv = d2 ? xb : xa;
            int dim = p + d2 * 4;
            float ex = __expf(-xv);
            float s  = __fdividef(xv, 1.f + ex);
            float t5 = fmaf(xv, 5.f, 8.f);
            float cf = floorf(t5);
            int   ci = (int)cf;
            float u  = t5 - cf;
            float um = 1.f - u;
            float u2 = u * u, um2 = um * um;
            float b0 = um2 * um * (1.f / 6.f);
            float b3 = u2 * u * (1.f / 6.f);
            float b1 = fmaf(u2, fmaf(u, 0.5f, -1.f), 2.f / 3.f);
            float b2 = fmaf(um2, fmaf(um, 0.5f, -1.f), 2.f / 3.f);
            int cic = ci < 0 ? 0 : (ci > 15 ? 15 : ci);
            bool ok = (ci == cic);                  // outside grid -> basis all zero
            unsigned short q0 = __half_as_ushort(__float2half_rn(ok ? b0 : 0.f));
            unsigned short q1 = __half_as_ushort(__float2half_rn(ok ? b1 : 0.f));
            unsigned short q2 = __half_as_ushort(__float2half_rn(ok ? b2 : 0.f));
            unsigned short q3 = __half_as_ushort(__float2half_rn(ok ? b3 : 0.f));
            unsigned short qs = __half_as_ushort(__float2half_rn(s));
            unsigned vl = VLUT[cic];
            unsigned base = aoff + (unsigned)tok * APITCH + dim * 16;
            #pragma unroll
            for (int gi = 0; gi < 4; ++gi) {
                unsigned s0 = (vl >> (8 * gi)) & 0xF;
                unsigned s1 = (vl >> (8 * gi + 4)) & 0xF;
                unsigned short lo = s0 == 0 ? q0 : s0 == 1 ? q1 : s0 == 2 ? q2
                                  : s0 == 3 ? q3 : s0 == 4 ? qs : (unsigned short)0;
                unsigned short hi = s1 == 0 ? q0 : s1 == 1 ? q1 : s1 == 2 ? q2
                                  : s1 == 3 ? q3 : s1 == 4 ? qs : (unsigned short)0;
                *(unsigned*)(smem + base + gi * 4) = (unsigned)lo | ((unsigned)hi << 16);
            }
            *(unsigned short*)(smem + moff + (dim * 64 + tok) * 2) = MLUT[cic];
        }
    };

    // prologue: A(0)+meta(0); x pipeline distance 2
    float xaN, xbN;
    {
        float xa0 = __ldg(xpa), xb0 = __ldg(xpb);
        buildA(SM_A0, SM_META, xa0, xb0);
        xaN = __ldg(xpa + 8u * 65536u);
        xbN = __ldg(xpb + 8u * 65536u);
    }

    for (int c = 0; c < NCHUNK; ++c) {
        const int buf = c & 1;
        const unsigned ab = sb + (buf ? SM_A1 : SM_A0) + (unsigned)g * (16 * APITCH);

        asm volatile("cp.async.wait_group 0;" ::: "memory");
        __syncthreads();

        if (c + 1 < NCHUNK) cpW(c + 1, (c + 1) & 1);

        // ---- sparse MMA(c): 4 dim-pairs (k32) x 8 n8-groups ----
        unsigned a[4][4], e[4];
        #pragma unroll
        for (int dp = 0; dp < 4; ++dp)
            LDSM_X4(a[dp], ab + dp * 32 + paL);
        const unsigned short* mArr =
            (const unsigned short*)(smem + SM_META + buf * 1024);
        #pragma unroll
        for (int dp = 0; dp < 4; ++dp) {
            int di = 2 * dp + (l & 1);
            unsigned m0 = mArr[di * 64 + g * 16 + (l >> 2)];
            unsigned m1 = mArr[di * 64 + g * 16 + (l >> 2) + 8];
            e[dp] = m0 | (m1 << 16);
        }
        const unsigned wbW = sb + SM_W + buf * WBUF + (unsigned)h * (64 * WPITCH);
        #pragma unroll
        for (int ng = 0; ng < 8; ++ng) {
            #pragma unroll
            for (int dp = 0; dp < 4; ++dp) {
                unsigned b[4];
                LDSM_X4(b, wbW + ng * (8 * WPITCH) + dp * 64 + pbL);
                MMASP(acc[ng], a[dp], b, e[dp]);
            }
        }

        // ---- x(c+2) loads + build A(c+1)/meta(c+1) (overlaps MMA drain) ----
        float xa2 = 0.f, xb2 = 0.f;
        if (c + 2 < NCHUNK) {
            xa2 = __ldg(xpa + (size_t)(8 * (c + 2)) * 65536u);
            xb2 = __ldg(xpb + (size_t)(8 * (c + 2)) * 65536u);
        }
        if (c + 1 < NCHUNK)
            buildA(((c + 1) & 1) ? SM_A1 : SM_A0, SM_META + ((c + 1) & 1) * 1024,
                   xaN, xbN);
        xaN = xa2; xbN = xb2;
    }

    // ---------------- epilogue: LN (cross n-half) + gamma/beta + residual ----
    float s0 = 0.f, q0 = 0.f, s1 = 0.f, q1 = 0.f;
    #pragma unroll
    for (int t = 0; t < 8; ++t) {
        s0 += acc[t][0] + acc[t][1];
        q0 = fmaf(acc[t][0], acc[t][0], fmaf(acc[t][1], acc[t][1], q0));
        s1 += acc[t][2] + acc[t][3];
        q1 = fmaf(acc[t][2], acc[t][2], fmaf(acc[t][3], acc[t][3], q1));
    }
    #pragma unroll
    for (int m = 1; m <= 2; m <<= 1) {
        s0 += __shfl_xor_sync(0xffffffffu, s0, m);
        q0 += __shfl_xor_sync(0xffffffffu, q0, m);
        s1 += __shfl_xor_sync(0xffffffffu, s1, m);
        q1 += __shfl_xor_sync(0xffffffffu, q1, m);
    }
    float2* epi = (float2*)(smem + SM_EPI);
    const int tr = g * 16 + (l >> 2);
    if ((l & 3) == 0) {
        epi[tr * 2 + h]       = make_float2(s0, q0);
        epi[(tr + 8) * 2 + h] = make_float2(s1, q1);
    }
    __syncthreads();
    float2 o0 = epi[tr * 2 + (h ^ 1)];
    float2 o1 = epi[(tr + 8) * 2 + (h ^ 1)];
    float mu0 = (s0 + o0.x) * (1.f / 128.f);
    float rs0 = rsqrtf(fmaf(q0 + o0.y, 1.f / 128.f, -mu0 * mu0) + LN_EPS);
    float mu1 = (s1 + o1.x) * (1.f / 128.f);
    float rs1 = rsqrtf(fmaf(q1 + o1.y, 1.f / 128.f, -mu1 * mu1) + LN_EPS);

    const int r0 = tokbase + tr;
    const int r1 = r0 + 8;
    const float* x0 = x + (size_t)r0 * 128;
    const float* x1 = x + (size_t)r1 * 128;
    float* out0 = out + (size_t)r0 * 128;
    float* out1 = out + (size_t)r1 * 128;
    #pragma unroll
    for (int t = 0; t < 8; ++t) {
        int n = h * 64 + t * 8 + (l & 3) * 2;
        float4 gb = *(const float4*)(smem + SM_GB + n * 8);
        float2 xa = *(const float2*)(x0 + n);
        float2 xb = *(const float2*)(x1 + n);
        float2 oa, ob;
        oa.x = fmaf((acc[t][0] - mu0) * rs0, gb.x, gb.y) + xa.x;
        oa.y = fmaf((acc[t][1] - mu0) * rs0, gb.z, gb.w) + xa.y;
        ob.x = fmaf((acc[t][2] - mu1) * rs1, gb.x, gb.y) + xb.x;
        ob.y = fmaf((acc[t][3] - mu1) * rs1, gb.z, gb.w) + xb.y;
        *(float2*)(out0 + n) = oa;
        *(float2*)(out1 + n) = ob;
    }
}

// -------------------------------------------------------------------- launch
extern "C" void kernel_launch(void* const* d_in, const int* in_sizes, int n_in,
                              void* d_out, int out_size) {
    const float* x        = (const float*)d_in[0];
    const float* base_w   = (const float*)d_in[2];
    const float* spline_w = (const float*)d_in[3];
    const float* gamma    = (const float*)d_in[4];
    const float* beta     = (const float*)d_in[5];
    float* out            = (float*)d_out;

    dim3 tb(32, 8);
    transpose_x<<<dim3(2048, 4), tb>>>(x);
    prep_w<<<1088, 256>>>(base_w, spline_w);
    cudaFuncSetAttribute(kan_mma, cudaFuncAttributeMaxDynamicSharedMemorySize, SM_TOT);
    kan_mma<<<NCTA, 256, SM_TOT>>>(x, gamma, beta, out);
}

// round 15
// speedup vs baseline: 2.1523x; 2.1523x over previous
#include <cuda_runtime.h>
#include <cuda_fp16.h>
#include <cstdint>

// ResidualKANBlock via mma.sync (m16n8k16 f16, f32 accum).
// R14: transpose_x ELIMINATED — A-build threads remapped (tok=tid>>2, p=tid&3)
// so direct x LDGs touch 8 sectors/warp; distance-2 register pipeline hides them.
// Dense K=1792 (14 slots/dim, 8-dim chunks), warp n-split (TM=64), 16 chunks.

#define NTOK   65536
#define TM     64
#define NCTA   (NTOK / TM)            // 1024
#define NCHUNK 16                     // 8 input dims per chunk (K=112 slots)
#define LN_EPS 1e-5f

#define PITCH  240                    // bytes/row; 16B-aligned, bank-safe
#define ABUF   (64 * PITCH)
#define WBUF   (128 * PITCH)
#define SM_A0  0
#define SM_A1  ABUF
#define SM_W   (2 * ABUF)
#define SM_GB  (SM_W + 2 * WBUF)
#define SM_EPI (SM_GB + 1024)
#define SM_TOT (SM_EPI + 1024)        // ~94.2 KB -> occupancy 2

__device__ unsigned short g_W[NCHUNK * 128 * (PITCH/2)];  // per-chunk padded fp16 image

__device__ __forceinline__ unsigned s2u(const void* p) {
    unsigned r;
    asm("{ .reg .u64 t; cvta.to.shared.u64 t, %1; cvt.u32.u64 %0, t; }" : "=r"(r) : "l"(p));
    return r;
}

#define LDSM_X4(r, a) \
    asm volatile("ldmatrix.sync.aligned.m8n8.x4.shared.b16 {%0,%1,%2,%3}, [%4];" \
                 : "=r"((r)[0]), "=r"((r)[1]), "=r"((r)[2]), "=r"((r)[3]) : "r"(a))
#define MMA16816(d, a, b0, b1) \
    asm volatile("mma.sync.aligned.m16n8k16.row.col.f32.f16.f16.f32 " \
                 "{%0,%1,%2,%3}, {%4,%5,%6,%7}, {%8,%9}, {%0,%1,%2,%3};" \
                 : "+f"((d)[0]), "+f"((d)[1]), "+f"((d)[2]), "+f"((d)[3]) \
                 : "r"((a)[0]), "r"((a)[1]), "r"((a)[2]), "r"((a)[3]), "r"(b0), "r"(b1))
#define CPASYNC16(dst, src) \
    asm volatile("cp.async.cg.shared.global [%0], [%1], 16;" :: "r"(dst), "l"(src) : "memory")

// ------------------------------------------------------------- prep kernel
__global__ void prep_w(const float* __restrict__ base_w,
                       const float* __restrict__ spline_w) {
    int idx = blockIdx.x * blockDim.x + threadIdx.x;
    if (idx >= NCHUNK * 128 * (PITCH / 2)) return;
    int c = idx / (128 * (PITCH / 2));
    int r = idx % (128 * (PITCH / 2));
    int n = r / (PITCH / 2);
    int s = r % (PITCH / 2);           // slot in row (0..119; 112 live)
    float v = 0.f;
    if (s < 112) {
        int d = s / 14, jj = s - d * 14, i = 8 * c + d;
        if (jj < 13) v = spline_w[(size_t)n * 1664 + i * 13 + jj];
        else         v = base_w[n * 128 + i];
    }
    g_W[(size_t)c * (128 * (PITCH/2)) + n * (PITCH/2) + s] =
        __half_as_ushort(__float2half_rn(v));
}

// --------------------------------------------------------------- main kernel
__global__ void __launch_bounds__(256, 2)
kan_mma(const float* __restrict__ x, const float* __restrict__ gamma,
        const float* __restrict__ beta, float* __restrict__ out)
{
    extern __shared__ unsigned char smem[];
    const unsigned sb = s2u(smem);
    const int tid = threadIdx.x;
    const int w = tid >> 5, l = tid & 31;
    const int g = w >> 1, h = w & 1;            // token group / n-half
    const int tok = tid >> 2, p = tid & 3;      // A-build: token (0..63), dim-class (0..3)
    const int tokbase = blockIdx.x * TM;

    if (tid < 128) {
        float2 gb = make_float2(gamma[tid], beta[tid]);
        *(float2*)(smem + SM_GB + tid * 8) = gb;
    }

    const unsigned paBase = (unsigned)(g * 16 + (l & 15)) * PITCH + ((l >> 4) & 1) * 16;
    const unsigned pbBase = (unsigned)(((l >> 4) & 1) * 8 + (l & 7)) * PITCH + ((l >> 3) & 1) * 16;
    const unsigned hOff = (unsigned)h * 64 * PITCH;

    float acc[8][4];
    #pragma unroll
    for (int t = 0; t < 8; ++t)
        acc[t][0] = acc[t][1] = acc[t][2] = acc[t][3] = 0.f;

    auto cpW = [&](int c, int buf) {
        const char* src = (const char*)(g_W + (size_t)c * (128 * (PITCH/2)));
        unsigned dst = sb + SM_W + buf * WBUF;
        #pragma unroll
        for (int k = 0; k < 8; ++k) {
            int i16 = tid + 256 * k;
            if (i16 < WBUF / 16) CPASYNC16(dst + 16 * i16, src + 16 * i16);
        }
        asm volatile("cp.async.commit_group;" ::: "memory");
    };
    cpW(0, 0);

    // direct x pointer: row-major; this thread reads dims 8c+p and 8c+p+4
    const float* xq = x + (size_t)(tokbase + tok) * 128 + p;

    auto buildA = [&](unsigned aoff, float xa, float xb) {
        #pragma unroll
        for (int d2 = 0; d2 < 2; ++d2) {
            float xv = d2 ? xb : xa;
            int dim = p + d2 * 4;
            float ex = __expf(-xv);
            float s  = __fdividef(xv, 1.f + ex);            // silu
            float t5 = fmaf(xv, 5.f, 8.f);
            float cf = floorf(t5);
            int   ci = (int)cf;
            float u  = t5 - cf;
            float um = 1.f - u;
            float u2 = u * u, um2 = um * um;
            float b0 = um2 * um * (1.f / 6.f);
            float b3 = u2 * u * (1.f / 6.f);
            float b1 = fmaf(u2, fmaf(u, 0.5f, -1.f), 2.f / 3.f);
            float b2 = fmaf(um2, fmaf(um, 0.5f, -1.f), 2.f / 3.f);
            unsigned char* rowb = smem + aoff + (unsigned)tok * PITCH + dim * 28;
            #pragma unroll
            for (int z = 0; z < 7; ++z) ((unsigned*)rowb)[z] = 0u;      // zero 14 slots
            unsigned short* r16 = (unsigned short*)rowb;
            r16[13] = __half_as_ushort(__float2half_rn(s));
            int j0 = ci - 3;
            unsigned short h0 = __half_as_ushort(__float2half_rn(b0));
            unsigned short h1 = __half_as_ushort(__float2half_rn(b1));
            unsigned short h2 = __half_as_ushort(__float2half_rn(b2));
            unsigned short h3 = __half_as_ushort(__float2half_rn(b3));
            if ((unsigned)(j0 + 0) <= 12u) r16[j0 + 0] = h0;
            if ((unsigned)(j0 + 1) <= 12u) r16[j0 + 1] = h1;
            if ((unsigned)(j0 + 2) <= 12u) r16[j0 + 2] = h2;
            if ((unsigned)(j0 + 3) <= 12u) r16[j0 + 3] = h3;
        }
    };

    // zero tail pad of A rows once (slots 112..119 = 16 bytes at offset 224)
    if (p == 0) {
        *(uint4*)(smem + SM_A0 + (unsigned)tok * PITCH + 224) = make_uint4(0, 0, 0, 0);
        *(uint4*)(smem + SM_A1 + (unsigned)tok * PITCH + 224) = make_uint4(0, 0, 0, 0);
    }

    // prologue: A(0) + x pipeline (distance 2)
    float xaN, xbN;
    {
        float xa0 = __ldg(xq), xb0 = __ldg(xq + 4);
        buildA(SM_A0, xa0, xb0);
        xaN = __ldg(xq + 8);
        xbN = __ldg(xq + 12);
    }

    for (int c = 0; c < NCHUNK; ++c) {
        const unsigned ab = sb + ((c & 1) ? SM_A1 : SM_A0);

        asm volatile("cp.async.wait_group 0;" ::: "memory");   // W(c) resident
        __syncthreads();                                       // A(c)+W(c) visible; buf free

        if (c + 1 < NCHUNK) cpW(c + 1, (c + 1) & 1);           // safe: last read at c-1

        // ---- MMA(c): 7 k-steps x 4 n16-groups (this warp's n-half) ----
        const unsigned wb = sb + SM_W + (c & 1) * WBUF + hOff;
        unsigned a[7][4];
        #pragma unroll
        for (int ks = 0; ks < 7; ++ks) LDSM_X4(a[ks], ab + paBase + ks * 32);
        #pragma unroll
        for (int ng = 0; ng < 4; ++ng) {
            const unsigned base = wb + ng * 16 * PITCH + pbBase;
            #pragma unroll
            for (int ks = 0; ks < 7; ++ks) {
                unsigned b[4];
                LDSM_X4(b, base + ks * 32);
                MMA16816(acc[ng * 2],     a[ks], b[0], b[1]);
                MMA16816(acc[ng * 2 + 1], a[ks], b[2], b[3]);
            }
        }

        // ---- x(c+2) loads, then build A(c+1) (overlaps MMA latency) ----
        float xa2 = 0.f, xb2 = 0.f;
        if (c + 2 < NCHUNK) {
            xa2 = __ldg(xq + 8 * (c + 2));
            xb2 = __ldg(xq + 8 * (c + 2) + 4);
        }
        if (c + 1 < NCHUNK)
            buildA(((c + 1) & 1) ? SM_A1 : SM_A0, xaN, xbN);
        xaN = xa2; xbN = xb2;
    }

    // ---------------- epilogue: LN (cross n-half) + gamma/beta + residual ----
    float s0 = 0.f, q0 = 0.f, s1 = 0.f, q1 = 0.f;
    #pragma unroll
    for (int t = 0; t < 8; ++t) {
        s0 += acc[t][0] + acc[t][1];
        q0 = fmaf(acc[t][0], acc[t][0], fmaf(acc[t][1], acc[t][1], q0));
        s1 += acc[t][2] + acc[t][3];
        q1 = fmaf(acc[t][2], acc[t][2], fmaf(acc[t][3], acc[t][3], q1));
    }
    #pragma unroll
    for (int m = 1; m <= 2; m <<= 1) {
        s0 += __shfl_xor_sync(0xffffffffu, s0, m);
        q0 += __shfl_xor_sync(0xffffffffu, q0, m);
        s1 += __shfl_xor_sync(0xffffffffu, s1, m);
        q1 += __shfl_xor_sync(0xffffffffu, q1, m);
    }
    float2* epi = (float2*)(smem + SM_EPI);
    const int tr = g * 16 + (l >> 2);
    if ((l & 3) == 0) {
        epi[tr * 2 + h]       = make_float2(s0, q0);
        epi[(tr + 8) * 2 + h] = make_float2(s1, q1);
    }
    __syncthreads();
    float2 o0 = epi[tr * 2 + (h ^ 1)];
    float2 o1 = epi[(tr + 8) * 2 + (h ^ 1)];
    float mu0 = (s0 + o0.x) * (1.f / 128.f);
    float rs0 = rsqrtf(fmaf(q0 + o0.y, 1.f / 128.f, -mu0 * mu0) + LN_EPS);
    float mu1 = (s1 + o1.x) * (1.f / 128.f);
    float rs1 = rsqrtf(fmaf(q1 + o1.y, 1.f / 128.f, -mu1 * mu1) + LN_EPS);

    const int r0 = tokbase + tr;
    const int r1 = r0 + 8;
    const float* x0 = x + (size_t)r0 * 128;
    const float* x1 = x + (size_t)r1 * 128;
    float* out0 = out + (size_t)r0 * 128;
    float* out1 = out + (size_t)r1 * 128;
    #pragma unroll
    for (int t = 0; t < 8; ++t) {
        int n = h * 64 + (t >> 1) * 16 + (t & 1) * 8 + (l & 3) * 2;
        float4 gb = *(const float4*)(smem + SM_GB + n * 8);
        float2 xa = *(const float2*)(x0 + n);
        float2 xb = *(const float2*)(x1 + n);
        float2 oa, ob;
        oa.x = fmaf((acc[t][0] - mu0) * rs0, gb.x, gb.y) + xa.x;
        oa.y = fmaf((acc[t][1] - mu0) * rs0, gb.z, gb.w) + xa.y;
        ob.x = fmaf((acc[t][2] - mu1) * rs1, gb.x, gb.y) + xb.x;
        ob.y = fmaf((acc[t][3] - mu1) * rs1, gb.z, gb.w) + xb.y;
        *(float2*)(out0 + n) = oa;
        *(float2*)(out1 + n) = ob;
    }
}

// -------------------------------------------------------------------- launch
extern "C" void kernel_launch(void* const* d_in, const int* in_sizes, int n_in,
                              void* d_out, int out_size) {
    const float* x        = (const float*)d_in[0];
    const float* base_w   = (const float*)d_in[2];
    const float* spline_w = (const float*)d_in[3];
    const float* gamma    = (const float*)d_in[4];
    const float* beta     = (const float*)d_in[5];
    float* out            = (float*)d_out;

    prep_w<<<960, 256>>>(base_w, spline_w);
    cudaFuncSetAttribute(kan_mma, cudaFuncAttributeMaxDynamicSharedMemorySize, SM_TOT);
    kan_mma<<<NCTA, 256, SM_TOT>>>(x, gamma, beta, out);
}

// round 17
// speedup vs baseline: 2.3472x; 1.0906x over previous
#include <cuda_runtime.h>
#include <cuda_fp16.h>
#include <cstdint>

// ResidualKANBlock via mma.sync (m16n8k16 f16, f32 accum).
// R15: warp tile rebalanced to M32xN32 (2 token-halves x 4 n-quarters) —
// minimizes ldmatrix bytes (L1 is the measured binding pipe at 82.5%).
// Per k-step: 2 A + 2 B fragment loads, 8 MMAs, registers transient.

#define NTOK   65536
#define TM     64
#define NCTA   (NTOK / TM)            // 1024
#define NCHUNK 16                     // 8 input dims per chunk (K=112 slots)
#define LN_EPS 1e-5f

#define PITCH  240                    // bytes/row; 16B-aligned, bank-safe
#define ABUF   (64 * PITCH)
#define WBUF   (128 * PITCH)
#define SM_A0  0
#define SM_A1  ABUF
#define SM_W   (2 * ABUF)
#define SM_GB  (SM_W + 2 * WBUF)
#define SM_EPI (SM_GB + 1024)
#define SM_TOT (SM_EPI + 2048)        // ~95 KB -> occupancy 2

__device__ unsigned short g_W[NCHUNK * 128 * (PITCH/2)];  // per-chunk padded fp16 image

__device__ __forceinline__ unsigned s2u(const void* p) {
    unsigned r;
    asm("{ .reg .u64 t; cvta.to.shared.u64 t, %1; cvt.u32.u64 %0, t; }" : "=r"(r) : "l"(p));
    return r;
}

#define LDSM_X4(r, a) \
    asm volatile("ldmatrix.sync.aligned.m8n8.x4.shared.b16 {%0,%1,%2,%3}, [%4];" \
                 : "=r"((r)[0]), "=r"((r)[1]), "=r"((r)[2]), "=r"((r)[3]) : "r"(a))
#define MMA16816(d, a, b0, b1) \
    asm volatile("mma.sync.aligned.m16n8k16.row.col.f32.f16.f16.f32 " \
                 "{%0,%1,%2,%3}, {%4,%5,%6,%7}, {%8,%9}, {%0,%1,%2,%3};" \
                 : "+f"((d)[0]), "+f"((d)[1]), "+f"((d)[2]), "+f"((d)[3]) \
                 : "r"((a)[0]), "r"((a)[1]), "r"((a)[2]), "r"((a)[3]), "r"(b0), "r"(b1))
#define CPASYNC16(dst, src) \
    asm volatile("cp.async.cg.shared.global [%0], [%1], 16;" :: "r"(dst), "l"(src) : "memory")

// ------------------------------------------------------------- prep kernel
__global__ void prep_w(const float* __restrict__ base_w,
                       const float* __restrict__ spline_w) {
    int idx = blockIdx.x * blockDim.x + threadIdx.x;
    if (idx >= NCHUNK * 128 * (PITCH / 2)) return;
    int c = idx / (128 * (PITCH / 2));
    int r = idx % (128 * (PITCH / 2));
    int n = r / (PITCH / 2);
    int s = r % (PITCH / 2);           // slot in row (0..119; 112 live)
    float v = 0.f;
    if (s < 112) {
        int d = s / 14, jj = s - d * 14, i = 8 * c + d;
        if (jj < 13) v = spline_w[(size_t)n * 1664 + i * 13 + jj];
        else         v = base_w[n * 128 + i];
    }
    g_W[(size_t)c * (128 * (PITCH/2)) + n * (PITCH/2) + s] =
        __half_as_ushort(__float2half_rn(v));
}

// --------------------------------------------------------------- main kernel
__global__ void __launch_bounds__(256, 2)
kan_mma(const float* __restrict__ x, const float* __restrict__ gamma,
        const float* __restrict__ beta, float* __restrict__ out)
{
    extern __shared__ unsigned char smem[];
    const unsigned sb = s2u(smem);
    const int tid = threadIdx.x;
    const int w = tid >> 5, l = tid & 31;
    const int gm = w >> 2, q = w & 3;           // token-half / n-quarter
    const int tok = tid >> 2, p = tid & 3;      // A-build: token, dim-class
    const int tokbase = blockIdx.x * TM;

    if (tid < 128) {
        float2 gb = make_float2(gamma[tid], beta[tid]);
        *(float2*)(smem + SM_GB + tid * 8) = gb;
    }

    const unsigned paBase = (unsigned)(gm * 32 + (l & 15)) * PITCH + ((l >> 4) & 1) * 16;
    const unsigned pbBase = (unsigned)(q * 32 + ((l >> 4) & 1) * 8 + (l & 7)) * PITCH
                          + ((l >> 3) & 1) * 16;

    float acc[8][4];   // [mt*4 + n16*2 + half][d0..d3]
    #pragma unroll
    for (int t = 0; t < 8; ++t)
        acc[t][0] = acc[t][1] = acc[t][2] = acc[t][3] = 0.f;

    auto cpW = [&](int c, int buf) {
        const char* src = (const char*)(g_W + (size_t)c * (128 * (PITCH/2)));
        unsigned dst = sb + SM_W + buf * WBUF;
        #pragma unroll
        for (int k = 0; k < 8; ++k) {
            int i16 = tid + 256 * k;
            if (i16 < WBUF / 16) CPASYNC16(dst + 16 * i16, src + 16 * i16);
        }
        asm volatile("cp.async.commit_group;" ::: "memory");
    };
    cpW(0, 0);

    const float* xq = x + (size_t)(tokbase + tok) * 128 + p;

    auto buildA = [&](unsigned aoff, float xa, float xb) {
        #pragma unroll
        for (int d2 = 0; d2 < 2; ++d2) {
            float xv = d2 ? xb : xa;
            int dim = p + d2 * 4;
            float ex = __expf(-xv);
            float s  = __fdividef(xv, 1.f + ex);            // silu
            float t5 = fmaf(xv, 5.f, 8.f);
            float cf = floorf(t5);
            int   ci = (int)cf;
            float u  = t5 - cf;
            float um = 1.f - u;
            float u2 = u * u, um2 = um * um;
            float b0 = um2 * um * (1.f / 6.f);
            float b3 = u2 * u * (1.f / 6.f);
            float b1 = fmaf(u2, fmaf(u, 0.5f, -1.f), 2.f / 3.f);
            float b2 = fmaf(um2, fmaf(um, 0.5f, -1.f), 2.f / 3.f);
            unsigned char* rowb = smem + aoff + (unsigned)tok * PITCH + dim * 28;
            #pragma unroll
            for (int z = 0; z < 7; ++z) ((unsigned*)rowb)[z] = 0u;
            unsigned short* r16 = (unsigned short*)rowb;
            r16[13] = __half_as_ushort(__float2half_rn(s));
            int j0 = ci - 3;
            unsigned short h0 = __half_as_ushort(__float2half_rn(b0));
            unsigned short h1 = __half_as_ushort(__float2half_rn(b1));
            unsigned short h2 = __half_as_ushort(__float2half_rn(b2));
            unsigned short h3 = __half_as_ushort(__float2half_rn(b3));
            if ((unsigned)(j0 + 0) <= 12u) r16[j0 + 0] = h0;
            if ((unsigned)(j0 + 1) <= 12u) r16[j0 + 1] = h1;
            if ((unsigned)(j0 + 2) <= 12u) r16[j0 + 2] = h2;
            if ((unsigned)(j0 + 3) <= 12u) r16[j0 + 3] = h3;
        }
    };

    if (p == 0) {
        *(uint4*)(smem + SM_A0 + (unsigned)tok * PITCH + 224) = make_uint4(0, 0, 0, 0);
        *(uint4*)(smem + SM_A1 + (unsigned)tok * PITCH + 224) = make_uint4(0, 0, 0, 0);
    }

    float xaN, xbN;
    {
        float xa0 = __ldg(xq), xb0 = __ldg(xq + 4);
        buildA(SM_A0, xa0, xb0);
        xaN = __ldg(xq + 8);
        xbN = __ldg(xq + 12);
    }

    for (int c = 0; c < NCHUNK; ++c) {
        const unsigned ab = sb + ((c & 1) ? SM_A1 : SM_A0);

        asm volatile("cp.async.wait_group 0;" ::: "memory");
        __syncthreads();

        if (c + 1 < NCHUNK) cpW(c + 1, (c + 1) & 1);

        // ---- MMA(c): per k-step load 2 A + 2 B fragments, 8 MMAs ----
        const unsigned abase = ab + paBase;
        const unsigned bbase = sb + SM_W + (c & 1) * WBUF + pbBase;
        #pragma unroll
        for (int ks = 0; ks < 7; ++ks) {
            unsigned a0[4], a1[4], b0[4], b1[4];
            LDSM_X4(a0, abase + ks * 32);
            LDSM_X4(a1, abase + 16 * PITCH + ks * 32);
            LDSM_X4(b0, bbase + ks * 32);
            LDSM_X4(b1, bbase + 16 * PITCH + ks * 32);
            MMA16816(acc[0], a0, b0[0], b0[1]);
            MMA16816(acc[1], a0, b0[2], b0[3]);
            MMA16816(acc[2], a0, b1[0], b1[1]);
            MMA16816(acc[3], a0, b1[2], b1[3]);
            MMA16816(acc[4], a1, b0[0], b0[1]);
            MMA16816(acc[5], a1, b0[2], b0[3]);
            MMA16816(acc[6], a1, b1[0], b1[1]);
            MMA16816(acc[7], a1, b1[2], b1[3]);
        }

        float xa2 = 0.f, xb2 = 0.f;
        if (c + 2 < NCHUNK) {
            xa2 = __ldg(xq + 8 * (c + 2));
            xb2 = __ldg(xq + 8 * (c + 2) + 4);
        }
        if (c + 1 < NCHUNK)
            buildA(((c + 1) & 1) ? SM_A1 : SM_A0, xaN, xbN);
        xaN = xa2; xbN = xb2;
    }

    // -------- epilogue: LN across 4 n-quarters + gamma/beta + residual ------
    // per thread: 4 row-partials (mt0-lo, mt0-hi, mt1-lo, mt1-hi) over 32 cols
    float rs_[4], sq_[4];
    #pragma unroll
    for (int mt = 0; mt < 2; ++mt) {
        float sl = 0.f, ql = 0.f, sh = 0.f, qh = 0.f;
        #pragma unroll
        for (int n8 = 0; n8 < 4; ++n8) {
            int t = mt * 4 + n8;
            sl += acc[t][0] + acc[t][1];
            ql = fmaf(acc[t][0], acc[t][0], fmaf(acc[t][1], acc[t][1], ql));
            sh += acc[t][2] + acc[t][3];
            qh = fmaf(acc[t][2], acc[t][2], fmaf(acc[t][3], acc[t][3], qh));
        }
        rs_[mt * 2] = sl;     sq_[mt * 2] = ql;
        rs_[mt * 2 + 1] = sh; sq_[mt * 2 + 1] = qh;
    }
    #pragma unroll
    for (int m = 1; m <= 2; m <<= 1) {
        #pragma unroll
        for (int k = 0; k < 4; ++k) {
            rs_[k] += __shfl_xor_sync(0xffffffffu, rs_[k], m);
            sq_[k] += __shfl_xor_sync(0xffffffffu, sq_[k], m);
        }
    }
    float2* epi = (float2*)(smem + SM_EPI);          // [64 tokens][4 quarters]
    const int rbase = gm * 32 + (l >> 2);            // local token of mt0-lo
    if ((l & 3) == 0) {
        epi[(rbase +  0) * 4 + q] = make_float2(rs_[0], sq_[0]);
        epi[(rbase +  8) * 4 + q] = make_float2(rs_[1], sq_[1]);
        epi[(rbase + 16) * 4 + q] = make_float2(rs_[2], sq_[2]);
        epi[(rbase + 24) * 4 + q] = make_float2(rs_[3], sq_[3]);
    }
    __syncthreads();

    float mu[4], rcs[4];
    #pragma unroll
    for (int k = 0; k < 4; ++k) {
        int t = rbase + k * 8;
        float2 e0 = epi[t * 4 + 0], e1 = epi[t * 4 + 1];
        float2 e2 = epi[t * 4 + 2], e3 = epi[t * 4 + 3];
        float s = e0.x + e1.x + e2.x + e3.x;
        float qq = e0.y + e1.y + e2.y + e3.y;
        mu[k] = s * (1.f / 128.f);
        rcs[k] = rsqrtf(fmaf(qq, 1.f / 128.f, -mu[k] * mu[k]) + LN_EPS);
    }

    #pragma unroll
    for (int t = 0; t < 8; ++t) {
        int mt = t >> 2, n8 = t & 3;
        int n = q * 32 + n8 * 8 + (l & 3) * 2;
        int rlo = tokbase + rbase + mt * 16;
        int rhi = rlo + 8;
        float4 gb = *(const float4*)(smem + SM_GB + n * 8);
        float2 xa = *(const float2*)(x + (size_t)rlo * 128 + n);
        float2 xb = *(const float2*)(x + (size_t)rhi * 128 + n);
        float m0 = mu[mt * 2], r0 = rcs[mt * 2];
        float m1 = mu[mt * 2 + 1], r1 = rcs[mt * 2 + 1];
        float2 oa, ob;
        oa.x = fmaf((acc[t][0] - m0) * r0, gb.x, gb.y) + xa.x;
        oa.y = fmaf((acc[t][1] - m0) * r0, gb.z, gb.w) + xa.y;
        ob.x = fmaf((acc[t][2] - m1) * r1, gb.x, gb.y) + xb.x;
        ob.y = fmaf((acc[t][3] - m1) * r1, gb.z, gb.w) + xb.y;
        *(float2*)(out + (size_t)rlo * 128 + n) = oa;
        *(float2*)(out + (size_t)rhi * 128 + n) = ob;
    }
}

// -------------------------------------------------------------------- launch
extern "C" void kernel_launch(void* const* d_in, const int* in_sizes, int n_in,
                              void* d_out, int out_size) {
    const float* x        = (const float*)d_in[0];
    const float* base_w   = (const float*)d_in[2];
    const float* spline_w = (const float*)d_in[3];
    const float* gamma    = (const float*)d_in[4];
    const float* beta     = (const float*)d_in[5];
    float* out            = (float*)d_out;

    prep_w<<<960, 256>>>(base_w, spline_w);
    cudaFuncSetAttribute(kan_mma, cudaFuncAttributeMaxDynamicSharedMemorySize, SM_TOT);
    kan_mma<<<NCTA, 256, SM_TOT>>>(x, gamma, beta, out);
}